// round 16
// baseline (speedup 1.0000x reference)
#include <cuda_runtime.h>
#include <cstdint>

// out[c, i, j, k, l] = tb[c,0,i] * tb[c,1,j] * tb[c,2,k] * tb[c,3,l]
// tb = tensor + bias, shapes (C=2048, 4, 16). Output (C, 16,16,16,16) fp32.
//
// Pure store-bandwidth kernel: 512 MB out, ~1 MB in.
// R16 combines the two best measured halves:
//  - block=128 (R14/R15): best in-window profile (ncu 73.5us, DRAM 82.1%)
//  - grid=16384 (R6/R12): wall-minus-ncu dispatch gap ~0.0-0.4us vs
//    ~2us at grid=32768 (6 samples vs 2, cleanly separated)
// Each CTA covers TWO i-slices (32 KB): 8 independent st.global.v8 per
// thread, smem-staged inputs, one barrier.

static constexpr int LDIM = 16;
static constexpr int NFAC = 4;
static constexpr int THREADS = 128;

__device__ __forceinline__ void stg_v8(float* p,
                                       float a, float b, float c, float d,
                                       float e, float f, float g, float h)
{
    asm volatile(
        "st.global.v8.b32 [%0], {%1, %2, %3, %4, %5, %6, %7, %8};"
        :: "l"(p),
           "r"(__float_as_uint(a)), "r"(__float_as_uint(b)),
           "r"(__float_as_uint(c)), "r"(__float_as_uint(d)),
           "r"(__float_as_uint(e)), "r"(__float_as_uint(f)),
           "r"(__float_as_uint(g)), "r"(__float_as_uint(h))
        : "memory");
}

__global__ __launch_bounds__(THREADS)
void tpe_kernel(const float* __restrict__ tensor,
                const float* __restrict__ bias,
                float* __restrict__ out)
{
    __shared__ float s[NFAC * LDIM];

    const int b  = blockIdx.x;
    const int c  = b >> 3;         // channel
    const int ih = b & 7;          // i-pair: slices i0 = 2*ih, i0+1
    const int t  = threadIdx.x;

    if (t < NFAC * LDIM) {
        const int g = c * (NFAC * LDIM) + t;
        s[t] = tensor[g] + bias[g];
    }
    __syncthreads();

    // Within one i-slice (512 float8s), r = t + 128*mm, mm in [0,4):
    //   lh = r & 1, k = (r>>1) & 15   (fixed per thread, from t)
    //   j  = (r>>5) & 15 = ((t>>5) & 3) | (mm << 2)
    const int lh   = t & 1;
    const int k    = (t >> 1) & 15;
    const int jlow = (t >> 5) & 3;

    const float p2 = s[2 * LDIM + k];
    float v3[8];
    #pragma unroll
    for (int m = 0; m < 8; ++m) v3[m] = s[3 * LDIM + lh * 8 + m];

    const int   i0 = ih << 1;
    const float a0 = s[i0]     * p2;   // slice i0
    const float a1 = s[i0 + 1] * p2;   // slice i0+1

    float* ob = out + (size_t)c * 65536 + (size_t)i0 * 4096 + (size_t)t * 8;

    #pragma unroll
    for (int mm = 0; mm < 4; ++mm) {
        const float sj = s[LDIM + jlow + (mm << 2)];
        const float aA = a0 * sj;
        const float aB = a1 * sj;
        float* p0 = ob + (size_t)mm * 1024;
        stg_v8(p0,
               aA * v3[0], aA * v3[1], aA * v3[2], aA * v3[3],
               aA * v3[4], aA * v3[5], aA * v3[6], aA * v3[7]);
        stg_v8(p0 + 4096,
               aB * v3[0], aB * v3[1], aB * v3[2], aB * v3[3],
               aB * v3[4], aB * v3[5], aB * v3[6], aB * v3[7]);
    }
}

extern "C" void kernel_launch(void* const* d_in, const int* in_sizes, int n_in,
                              void* d_out, int out_size)
{
    const float* tensor = (const float*)d_in[0];
    const float* bias   = (const float*)d_in[1];
    float* out          = (float*)d_out;

    const int C = in_sizes[0] / (NFAC * LDIM);   // 2048

    tpe_kernel<<<C * 8, THREADS>>>(tensor, bias, out);
}

// round 17
// speedup vs baseline: 1.0304x; 1.0304x over previous
#include <cuda_runtime.h>
#include <cstdint>

// out[c, i, j, k, l] = tb[c,0,i] * tb[c,1,j] * tb[c,2,k] * tb[c,3,l]
// tb = tensor + bias, shapes (C=2048, 4, 16). Output (C, 16,16,16,16) fp32.
//
// FINAL converged kernel (= R15; session best: ncu 73.47us, DRAM 82.1%,
// wall 75.87us -- tied with R7 inside run noise).
//
// Pure store-bandwidth kernel: 512 MB out, ~1 MB in. Converged config:
//  - 32768 CTAs x 128 threads; each CTA writes one contiguous 16 KB
//    i-slice out[c, i, :, :, :]. 13.5-wave schedule at 16 CTAs/SM;
//    measured best in-window across grains 256KB..16KB (R1..R7) and
//    block shapes 512/256/128 (R11..R15).
//  - smem-staged inputs (64 floats, one barrier) -- beats direct
//    per-thread LDG (R8).
//  - 4 independent 256-bit st.global.v8.b32 per thread, perfectly
//    coalesced 128B lines (v8 beats v4, R4).
//  - plain STG egress: measured identical to 16KB-block and per-warp-1KB
//    cp.async.bulk (R9/R10) -- LTS/DRAM path-independent.
// Effective store rate 7.3 TB/s = 91% of HBM3e spec; wall floor ~75.8us =
// HBM-write-limited window + ~2us replay overhead (mapped R6/R7/R15/R16).

static constexpr int LDIM = 16;
static constexpr int NFAC = 4;
static constexpr int THREADS = 128;

__device__ __forceinline__ void stg_v8(float* p,
                                       float a, float b, float c, float d,
                                       float e, float f, float g, float h)
{
    asm volatile(
        "st.global.v8.b32 [%0], {%1, %2, %3, %4, %5, %6, %7, %8};"
        :: "l"(p),
           "r"(__float_as_uint(a)), "r"(__float_as_uint(b)),
           "r"(__float_as_uint(c)), "r"(__float_as_uint(d)),
           "r"(__float_as_uint(e)), "r"(__float_as_uint(f)),
           "r"(__float_as_uint(g)), "r"(__float_as_uint(h))
        : "memory");
}

__global__ __launch_bounds__(THREADS)
void tpe_kernel(const float* __restrict__ tensor,
                const float* __restrict__ bias,
                float* __restrict__ out)
{
    __shared__ float s[NFAC * LDIM];

    const int b = blockIdx.x;
    const int c = b >> 4;          // channel
    const int i = b & 15;          // i slice: this CTA writes out[c, i, :, :, :]
    const int t = threadIdx.x;

    if (t < NFAC * LDIM) {
        const int g = c * (NFAC * LDIM) + t;
        s[t] = tensor[g] + bias[g];
    }
    __syncthreads();

    // float8 index within the i-slice: r = t + 128*m, m in [0,4).
    //   lh = r & 1, k = (r>>1) & 15  (fixed per thread, from t);
    //   j = (r>>5) & 15 = ((t>>5) & 3) | (m << 2).
    const int lh   = t & 1;
    const int k    = (t >> 1) & 15;
    const int jlow = (t >> 5) & 3;

    const float p2 = s[2 * LDIM + k];
    float v3[8];
    #pragma unroll
    for (int m = 0; m < 8; ++m) v3[m] = s[3 * LDIM + lh * 8 + m];

    const float a0 = s[i] * p2;

    float* ob = out + (size_t)c * 65536 + (size_t)i * 4096 + (size_t)t * 8;

    #pragma unroll
    for (int m = 0; m < 4; ++m) {
        const float a = a0 * s[LDIM + jlow + (m << 2)];
        stg_v8(ob + (size_t)m * 1024,
               a * v3[0], a * v3[1], a * v3[2], a * v3[3],
               a * v3[4], a * v3[5], a * v3[6], a * v3[7]);
    }
}

extern "C" void kernel_launch(void* const* d_in, const int* in_sizes, int n_in,
                              void* d_out, int out_size)
{
    const float* tensor = (const float*)d_in[0];
    const float* bias   = (const float*)d_in[1];
    float* out          = (float*)d_out;

    const int C = in_sizes[0] / (NFAC * LDIM);   // 2048

    tpe_kernel<<<C * 16, THREADS>>>(tensor, bias, out);
}